// round 8
// baseline (speedup 1.0000x reference)
#include <cuda_runtime.h>
#include <math.h>

#define N_  16
#define C_  192
#define H_  64
#define W_  64
#define K_  64
#define HW_ (H_ * W_)
#define G_  4096
#define LIK_BOUND 1e-9f

#define PREP_BLOCKS   (C_ + 32)          // 192 LUT + 32 bucket blocks
#define QUANT_BLOCKS  (N_ * C_)          // 3072

// scratch: likelihood LUT [C,K], bucket table [G] (idx | 0x80 if impure)
__device__ float d_lut[C_ * K_];
__device__ __align__(16) unsigned char d_B[G_];
__device__ int d_ready;                  // prep completion counter
__device__ int d_exit;                   // quantize completion counter (for reset)

__device__ __forceinline__ float softplus_f(float v) {
    return (v > 20.0f) ? v : log1pf(expf(v));
}
__device__ __forceinline__ float sigmoid_f(float v) {
    return 1.0f / (1.0f + expf(-v));
}

// chain eval using pre-transformed weights in shared:
// w[0..2]=sp(m0)  w[3..29]=sp(m1,m2,m3)  w[30..32]=sp(m4)
// w[33..44]=tanh(f0..f3)  w[45..47]=b0  w[48..56]=b1,b2,b3  w[57]=b4
__device__ float eval_chain(float v, const float* __restrict__ w) {
    float h[3], nh[3];
    #pragma unroll
    for (int o = 0; o < 3; o++) {
        float z = w[o] * v + w[45 + o];
        z += w[33 + o] * tanhf(z);
        h[o] = z;
    }
    #pragma unroll
    for (int l = 0; l < 3; l++) {
        #pragma unroll
        for (int o = 0; o < 3; o++) {
            const float* mm = w + 3 + l * 9 + o * 3;
            float z = w[48 + l * 3 + o] + mm[0] * h[0] + mm[1] * h[1] + mm[2] * h[2];
            z += w[36 + l * 3 + o] * tanhf(z);
            nh[o] = z;
        }
        h[0] = nh[0]; h[1] = nh[1]; h[2] = nh[2];
    }
    return w[57] + w[30] * h[0] + w[31] * h[1] + w[32] * h[2];
}

// count-form nearest index at probe e (exact reference semantics)
__device__ __forceinline__ int nearest_cnt(float e, const float* __restrict__ s_cb) {
    int cnt = 0;
    #pragma unroll
    for (int j = 0; j < K_ - 1; j++)
        cnt += (fabsf(s_cb[j + 1] - e) < fabsf(s_cb[j] - e)) ? 1 : 0;
    return cnt;
}

__device__ __forceinline__ void lookup(float v,
                                       const float2* __restrict__ s_pair,
                                       const unsigned char* __restrict__ s_B,
                                       const float2* __restrict__ s_yl,
                                       float& y, float& l)
{
    int g = __float2int_rd(fmaf(v, 128.0f, 2048.0f));
    g = max(0, min(g, G_ - 1));
    int b = s_B[g];
    int j = b & 0x7f;
    if (b & 0x80) {
        // boundary bucket: exact reference predicate (monotone walk)
        float2 p = s_pair[j];
        while (fabsf(p.y - v) < fabsf(p.x - v)) { j++; p = s_pair[j]; }
    }
    float2 r = s_yl[j];
    y = r.x; l = r.y;
}

// Single fused kernel.
//   bid in [0, 192):        LUT for channel bid (128 active threads)
//   bid in [192, 224):      bucket table, 128 entries each
//   bid in [224, 224+3072): quantize one (n,c) slice after spin-wait on prep
__global__ void __launch_bounds__(256)
fused_kernel(const float* __restrict__ x,
             const float* __restrict__ cb,
             float* __restrict__ y_hat,
             float* __restrict__ lik,
             const float* __restrict__ m0, const float* __restrict__ m1,
             const float* __restrict__ m2, const float* __restrict__ m3,
             const float* __restrict__ m4,
             const float* __restrict__ b0, const float* __restrict__ b1,
             const float* __restrict__ b2, const float* __restrict__ b3,
             const float* __restrict__ b4,
             const float* __restrict__ f0, const float* __restrict__ f1,
             const float* __restrict__ f2, const float* __restrict__ f3)
{
    int t   = threadIdx.x;
    int bid = blockIdx.x;

    if (bid < C_) {
        // ---------------- LUT block ----------------
        __shared__ float w[58];
        __shared__ float ev[2][K_];
        int c = bid;
        if (t < 33) {
            float raw;
            if (t < 3)       raw = m0[c * 3 + t];
            else if (t < 12) raw = m1[c * 9 + (t - 3)];
            else if (t < 21) raw = m2[c * 9 + (t - 12)];
            else if (t < 30) raw = m3[c * 9 + (t - 21)];
            else             raw = m4[c * 3 + (t - 30)];
            w[t] = softplus_f(raw);
        } else if (t < 45) {
            int i = t - 33;
            const float* fp = (i < 3) ? f0 : (i < 6) ? f1 : (i < 9) ? f2 : f3;
            w[t] = tanhf(fp[c * 3 + (i % 3)]);
        } else if (t < 58) {
            int i = t - 45;
            float raw;
            if (i < 3)       raw = b0[c * 3 + i];
            else if (i < 6)  raw = b1[c * 3 + (i - 3)];
            else if (i < 9)  raw = b2[c * 3 + (i - 6)];
            else if (i < 12) raw = b3[c * 3 + (i - 9)];
            else             raw = b4[c];
            w[t] = raw;
        }
        __syncthreads();

        if (t < 128) {
            int k = t & 63;
            float off = (t < 64) ? -0.5f : 0.5f;
            ev[t >> 6][k] = eval_chain(cb[k] + off, w);
        }
        __syncthreads();

        if (t < K_) {
            float lower = ev[0][t], upper = ev[1][t];
            float s  = lower + upper;
            float sg = (s < 0.0f) ? 1.0f : ((s > 0.0f) ? -1.0f : 0.0f);
            float lk = fabsf(sigmoid_f(sg * upper) - sigmoid_f(sg * lower));
            d_lut[c * K_ + t] = fmaxf(lk, LIK_BOUND);
        }
        __syncthreads();
        if (t == 0) {
            __threadfence();
            atomicAdd(&d_ready, 1);
        }
    } else if (bid < PREP_BLOCKS) {
        // ---------------- bucket block ----------------
        __shared__ float s_cb[K_];
        if (t < K_) s_cb[t] = cb[t];
        __syncthreads();
        if (t < 128) {
            int g = (bid - C_) * 128 + t;
            // guards (2e-5) dominate bucket-map float rounding (~4e-6)
            float e_lo = -16.0f + (float)g       * 0.0078125f - 2e-5f;
            float e_hi = -16.0f + (float)(g + 1) * 0.0078125f + 2e-5f;
            int c_lo = nearest_cnt(e_lo, s_cb);
            int c_hi = nearest_cnt(e_hi, s_cb);
            d_B[g] = (unsigned char)(c_lo | ((c_lo == c_hi) ? 0 : 0x80));
        }
        __syncthreads();
        if (t == 0) {
            __threadfence();
            atomicAdd(&d_ready, 1);
        }
    } else {
        // ---------------- quantize block ----------------
        __shared__ float2 s_pair[K_];   // (cb[j], cb[j+1]); last has +inf sentinel
        __shared__ float2 s_yl[K_];     // (cb[j], lut[c][j])
        __shared__ __align__(16) unsigned char s_B[G_];

        int qbid = bid - PREP_BLOCKS;
        int c = qbid % C_;

        // prep-independent fill first
        if (t < K_) {
            float cv  = cb[t];
            float cvn = (t < K_ - 1) ? cb[t + 1] : __int_as_float(0x7f800000);
            s_pair[t] = make_float2(cv, cvn);
        }

        // wait for prep completion (plain L2 reads, no atomic RMW storm)
        if (t == 0) {
            while (*(volatile int*)&d_ready < PREP_BLOCKS) __nanosleep(64);
            __threadfence();
        }
        __syncthreads();

        if (t < K_)
            s_yl[t] = make_float2(s_pair[t].x, d_lut[c * K_ + t]);
        ((int4*)s_B)[t] = ((const int4*)d_B)[t];   // 256 * 16B = 4096B
        __syncthreads();

        size_t base = (size_t)qbid * HW_;
        const float4* xv = reinterpret_cast<const float4*>(x + base);
        float4* yv = reinterpret_cast<float4*>(y_hat + base);
        float4* lv = reinterpret_cast<float4*>(lik + base);

        #pragma unroll
        for (int it = 0; it < HW_ / 4 / 256; it++) {
            int j = t + it * 256;
            float4 xx = xv[j];
            float4 yy, ll;
            lookup(xx.x, s_pair, s_B, s_yl, yy.x, ll.x);
            lookup(xx.y, s_pair, s_B, s_yl, yy.y, ll.y);
            lookup(xx.z, s_pair, s_B, s_yl, yy.z, ll.z);
            lookup(xx.w, s_pair, s_B, s_yl, yy.w, ll.w);
            yv[j] = yy;
            lv[j] = ll;
        }

        // reset counters for next graph replay: last quantize block cleans up.
        // Every quantize block increments d_exit only after passing its wait,
        // so when the count hits QUANT_BLOCKS nobody still reads d_ready.
        __syncthreads();
        if (t == 0) {
            int e = atomicAdd(&d_exit, 1);
            if (e == QUANT_BLOCKS - 1) {
                d_ready = 0;
                d_exit  = 0;
                __threadfence();
            }
        }
    }
}

extern "C" void kernel_launch(void* const* d_in, const int* in_sizes, int n_in,
                              void* d_out, int out_size)
{
    const float* x  = (const float*)d_in[0];
    const float* cb = (const float*)d_in[1];

    const float *m0, *m1, *m2, *m3, *m4;
    const float *b0, *b1, *b2, *b3, *b4;
    const float *f0, *f1, *f2, *f3;

    if (in_sizes[3] == C_ * 9) {
        // signature order: m0..m4, b0..b4, f0..f3
        m0 = (const float*)d_in[2];  m1 = (const float*)d_in[3];
        m2 = (const float*)d_in[4];  m3 = (const float*)d_in[5];
        m4 = (const float*)d_in[6];
        b0 = (const float*)d_in[7];  b1 = (const float*)d_in[8];
        b2 = (const float*)d_in[9];  b3 = (const float*)d_in[10];
        b4 = (const float*)d_in[11];
        f0 = (const float*)d_in[12]; f1 = (const float*)d_in[13];
        f2 = (const float*)d_in[14]; f3 = (const float*)d_in[15];
    } else {
        // dict insertion order: m0,b0,f0, m1,b1,f1, ...
        m0 = (const float*)d_in[2];  b0 = (const float*)d_in[3];  f0 = (const float*)d_in[4];
        m1 = (const float*)d_in[5];  b1 = (const float*)d_in[6];  f1 = (const float*)d_in[7];
        m2 = (const float*)d_in[8];  b2 = (const float*)d_in[9];  f2 = (const float*)d_in[10];
        m3 = (const float*)d_in[11]; b3 = (const float*)d_in[12]; f3 = (const float*)d_in[13];
        m4 = (const float*)d_in[14]; b4 = (const float*)d_in[15];
    }

    float* out   = (float*)d_out;
    float* y_hat = out;
    float* lik   = out + (size_t)N_ * C_ * HW_;

    fused_kernel<<<PREP_BLOCKS + QUANT_BLOCKS, 256>>>(
        x, cb, y_hat, lik,
        m0, m1, m2, m3, m4,
        b0, b1, b2, b3, b4,
        f0, f1, f2, f3);
}